// round 13
// baseline (speedup 1.0000x reference)
#include <cuda_runtime.h>

// ---------------------------------------------------------------------------
// WindowAttention: x(2048,49,192) -> qkv gemm -> 6-head window attention with
// azimuthal + radial sinusoidal biases -> proj gemm.
// Round 12: 8x8-tile SGEMM (128 thr) + bias tables (13 sincos, not 2401) +
// float4-aligned smem in attention.
// ---------------------------------------------------------------------------

#define WH 7
#define WW 7
#define NWIN 49
#define NH 6
#define HD 32
#define DIM 192
#define BATCH 2048
#define MROWS (BATCH * NWIN)          // 100352
#define QK_SCALE 0.17677669529663687f // 32^-0.5
#define PI_F 3.14159265358979323846f

// Scratch (allocation-free rule: __device__ globals)
__device__ float g_q[(size_t)BATCH * NH * NWIN * HD];
__device__ float g_k[(size_t)BATCH * NH * NWIN * HD];
__device__ float g_v[(size_t)BATCH * NH * NWIN * HD];
__device__ float g_ctx[(size_t)MROWS * DIM];

// ---------------------------------------------------------------------------
// Tiled SGEMM: out[m][n] = sum_k A[m][k] * W[n][k] (+ bias[n])
// BM=128, BN=64, BK=16, 128 threads, 8x8 per-thread tile, global->reg prefetch.
// QKV=true: A = x, epilogue scatters into g_q (scaled), g_k, g_v.
// QKV=false: A = g_ctx, epilogue writes d_out with bias.
// 100352 = 784*128, 576 = 9*64, 192 = 3*64, K = 192 = 12*16 -> no bounds checks.
// ---------------------------------------------------------------------------
#define GBM 128
#define GBN 64
#define GBK 16

template <bool QKV>
__global__ __launch_bounds__(128) void gemm_kernel(
    const float* __restrict__ Ain, const float* __restrict__ W,
    const float* __restrict__ bias, float* __restrict__ out)
{
    const float* A = QKV ? Ain : g_ctx;

    __shared__ float As[GBK][GBM];
    __shared__ float Bs[GBK][GBN];

    const int tid = threadIdx.x;
    const int ty = tid >> 3;        // 0..15 (row group of 8)
    const int tx = tid & 7;         // 0..7  (col group of 8)
    const int m0 = blockIdx.y * GBM;
    const int n0 = blockIdx.x * GBN;

    // A: one full row of the K-tile per thread (16 floats = 4 float4)
    const float* Aptr = A + (size_t)(m0 + tid) * DIM;
    // W: half row (8 floats = 2 float4) per thread
    const int brow = tid & 63;
    const int bcol = (tid >> 6) << 3;   // 0 or 8
    const float* Wptr = W + (size_t)(n0 + brow) * DIM + bcol;

    float acc[8][8];
#pragma unroll
    for (int i = 0; i < 8; i++)
#pragma unroll
        for (int j = 0; j < 8; j++) acc[i][j] = 0.0f;

    float4 pa0 = *(const float4*)(Aptr + 0);
    float4 pa1 = *(const float4*)(Aptr + 4);
    float4 pa2 = *(const float4*)(Aptr + 8);
    float4 pa3 = *(const float4*)(Aptr + 12);
    float4 pb0 = *(const float4*)(Wptr + 0);
    float4 pb1 = *(const float4*)(Wptr + 4);

    for (int kk = 0; kk < DIM; kk += GBK) {
        // conflict-free STS: As[c][tid] consecutive across lanes
        As[0][tid]  = pa0.x; As[1][tid]  = pa0.y; As[2][tid]  = pa0.z; As[3][tid]  = pa0.w;
        As[4][tid]  = pa1.x; As[5][tid]  = pa1.y; As[6][tid]  = pa1.z; As[7][tid]  = pa1.w;
        As[8][tid]  = pa2.x; As[9][tid]  = pa2.y; As[10][tid] = pa2.z; As[11][tid] = pa2.w;
        As[12][tid] = pa3.x; As[13][tid] = pa3.y; As[14][tid] = pa3.z; As[15][tid] = pa3.w;
        Bs[bcol + 0][brow] = pb0.x; Bs[bcol + 1][brow] = pb0.y;
        Bs[bcol + 2][brow] = pb0.z; Bs[bcol + 3][brow] = pb0.w;
        Bs[bcol + 4][brow] = pb1.x; Bs[bcol + 5][brow] = pb1.y;
        Bs[bcol + 6][brow] = pb1.z; Bs[bcol + 7][brow] = pb1.w;
        __syncthreads();

        if (kk + GBK < DIM) {
            const int nk = kk + GBK;
            pa0 = *(const float4*)(Aptr + nk + 0);
            pa1 = *(const float4*)(Aptr + nk + 4);
            pa2 = *(const float4*)(Aptr + nk + 8);
            pa3 = *(const float4*)(Aptr + nk + 12);
            pb0 = *(const float4*)(Wptr + nk + 0);
            pb1 = *(const float4*)(Wptr + nk + 4);
        }

#pragma unroll
        for (int k = 0; k < GBK; k++) {
            float a[8], b[8];
            *(float4*)&a[0] = *(const float4*)&As[k][ty * 8];
            *(float4*)&a[4] = *(const float4*)&As[k][ty * 8 + 4];
            *(float4*)&b[0] = *(const float4*)&Bs[k][tx * 8];
            *(float4*)&b[4] = *(const float4*)&Bs[k][tx * 8 + 4];
#pragma unroll
            for (int i = 0; i < 8; i++)
#pragma unroll
                for (int j = 0; j < 8; j++)
                    acc[i][j] = fmaf(a[i], b[j], acc[i][j]);
        }
        __syncthreads();
    }

    const int m_base = m0 + ty * 8;
    const int n_base = n0 + tx * 8;

    if (QKV) {
        // n_base..n_base+7 never straddles a DIM-multiple (64 | 192 boundaries)
        const int which = n_base / DIM;
        const int rem0 = n_base - which * DIM;
#pragma unroll
        for (int i = 0; i < 8; i++) {
            int m = m_base + i;
            int b = m / NWIN;
            int nn = m - b * NWIN;
#pragma unroll
            for (int j = 0; j < 8; j++) {
                int rem = rem0 + j;
                float val = acc[i][j] + bias[which * DIM + rem];
                int h = rem >> 5;
                int d = rem & 31;
                size_t idx = (((size_t)b * NH + h) * NWIN + nn) * HD + d;
                if (which == 0)      g_q[idx] = val * QK_SCALE;
                else if (which == 1) g_k[idx] = val;
                else                 g_v[idx] = val;
            }
        }
    } else {
        float4 bb0 = *(const float4*)&bias[n_base];
        float4 bb1 = *(const float4*)&bias[n_base + 4];
#pragma unroll
        for (int i = 0; i < 8; i++) {
            int m = m_base + i;
            float4 o0, o1;
            o0.x = acc[i][0] + bb0.x; o0.y = acc[i][1] + bb0.y;
            o0.z = acc[i][2] + bb0.z; o0.w = acc[i][3] + bb0.w;
            o1.x = acc[i][4] + bb1.x; o1.y = acc[i][5] + bb1.y;
            o1.z = acc[i][6] + bb1.z; o1.w = acc[i][7] + bb1.w;
            *(float4*)&out[(size_t)m * DIM + n_base] = o0;
            *(float4*)&out[(size_t)m * DIM + n_base + 4] = o1;
        }
    }
}

// ---------------------------------------------------------------------------
// Attention: one block per (head h, window b). 256 threads.
// Bias fields collapse to two 13-entry tables (az, rr each in [-6,6]):
//   biasA[az+6] = a_p[wrap(az)]*cos(az*2pi/56) + b_p[wrap(az)]*sin(az*2pi/56)
//   biasR[rr+6] = a_r[wrap(rr)]*cos(D_b*rr*2pi/224) + b_r[wrap(rr)]*sin(...)
// Only 26 sincosf per block (was 4802). Smem padded to 36 for float4 loads.
// ---------------------------------------------------------------------------
__global__ __launch_bounds__(256) void attn_kernel(
    const float* __restrict__ Dptr,
    const float* __restrict__ a_p, const float* __restrict__ b_p,
    const float* __restrict__ a_r, const float* __restrict__ b_r)
{
    const int h = blockIdx.x;
    const int b = blockIdx.y;
    const int tid = threadIdx.x;

    __shared__ float qs[NWIN * 36];
    __shared__ float ks[NWIN * 36];
    __shared__ float vs[NWIN * 36];
    __shared__ float S[NWIN * NWIN];
    __shared__ float biasA[13], biasR[13];

    const size_t base = ((size_t)b * NH + h) * NWIN * HD;

    if (tid < 13) {
        int az = tid - 6;
        int aidx = az < 0 ? az + 13 : az;   // python-style wrap (mod 13)
        float s, c;
        sincosf((float)az * (2.0f * PI_F / 56.0f), &s, &c);
        biasA[tid] = a_p[aidx * NH + h] * c + b_p[aidx * NH + h] * s;
    } else if (tid >= 32 && tid < 45) {
        int v = tid - 32;
        int rr = v - 6;
        int ridx = rr < 0 ? rr + 13 : rr;
        float Db = Dptr[b];
        float s, c;
        sincosf(Db * (float)rr * (2.0f * PI_F / 224.0f), &s, &c);
        biasR[v] = a_r[ridx * NH + h] * c + b_r[ridx * NH + h] * s;
    }
    for (int t = tid; t < NWIN * HD; t += 256) {
        int r = t >> 5, c = t & 31;
        qs[r * 36 + c] = g_q[base + t];
        ks[r * 36 + c] = g_k[base + t];
        vs[r * 36 + c] = g_v[base + t];
    }
    __syncthreads();

    // S = q*k^T (q pre-scaled) + biasA + biasR
    for (int t = tid; t < NWIN * NWIN; t += 256) {
        int i = t / NWIN;
        int j = t - i * NWIN;
        const float* qr = qs + i * 36;
        const float* kr = ks + j * 36;
        float dot = 0.0f;
#pragma unroll
        for (int d4 = 0; d4 < 8; d4++) {
            float4 qv = *(const float4*)(qr + d4 * 4);
            float4 kv = *(const float4*)(kr + d4 * 4);
            dot = fmaf(qv.x, kv.x, dot);
            dot = fmaf(qv.y, kv.y, dot);
            dot = fmaf(qv.z, kv.z, dot);
            dot = fmaf(qv.w, kv.w, dot);
        }
        int ih = i / WW, iw = i - ih * WW;
        int jh = j / WW, jw = j - jh * WW;
        S[t] = dot + biasA[iw - jw + 6] + biasR[ih - jh + 6];
    }
    __syncthreads();

    // softmax: one warp per row
    const int warp = tid >> 5, lane = tid & 31;
    for (int row = warp; row < NWIN; row += 8) {
        float* Sr = S + row * NWIN;
        float v0 = Sr[lane];
        float v1 = (lane + 32 < NWIN) ? Sr[lane + 32] : -1e30f;
        float mx = fmaxf(v0, v1);
#pragma unroll
        for (int o = 16; o; o >>= 1)
            mx = fmaxf(mx, __shfl_xor_sync(0xffffffffu, mx, o));
        float e0 = expf(v0 - mx);
        float e1 = (lane + 32 < NWIN) ? expf(v1 - mx) : 0.0f;
        float sm = e0 + e1;
#pragma unroll
        for (int o = 16; o; o >>= 1)
            sm += __shfl_xor_sync(0xffffffffu, sm, o);
        float inv = 1.0f / sm;
        Sr[lane] = e0 * inv;
        if (lane + 32 < NWIN) Sr[lane + 32] = e1 * inv;
    }
    __syncthreads();

    // O = P * V -> ctx layout (b, n, h*32 + d). 196 threads, 8 outputs each.
    if (tid < 196) {
        int n = tid >> 2;
        int dq = (tid & 3) << 3;      // 0,8,16,24
        const float* Pr = S + n * NWIN;
        float4 o0 = {0.f, 0.f, 0.f, 0.f}, o1 = {0.f, 0.f, 0.f, 0.f};
#pragma unroll 7
        for (int m2 = 0; m2 < NWIN; m2++) {
            float p = Pr[m2];
            float4 v0 = *(const float4*)&vs[m2 * 36 + dq];
            float4 v1 = *(const float4*)&vs[m2 * 36 + dq + 4];
            o0.x = fmaf(p, v0.x, o0.x); o0.y = fmaf(p, v0.y, o0.y);
            o0.z = fmaf(p, v0.z, o0.z); o0.w = fmaf(p, v0.w, o0.w);
            o1.x = fmaf(p, v1.x, o1.x); o1.y = fmaf(p, v1.y, o1.y);
            o1.z = fmaf(p, v1.z, o1.z); o1.w = fmaf(p, v1.w, o1.w);
        }
        float* ctx = g_ctx + ((size_t)b * NWIN + n) * DIM + h * HD + dq;
        *(float4*)ctx = o0;
        *(float4*)(ctx + 4) = o1;
    }
}

// ---------------------------------------------------------------------------
extern "C" void kernel_launch(void* const* d_in, const int* in_sizes, int n_in,
                              void* d_out, int out_size)
{
    const float* x      = (const float*)d_in[0];
    const float* D      = (const float*)d_in[1];
    const float* qkv_w  = (const float*)d_in[2];
    const float* qkv_b  = (const float*)d_in[3];
    const float* proj_w = (const float*)d_in[4];
    const float* proj_b = (const float*)d_in[5];
    const float* a_p    = (const float*)d_in[6];
    const float* b_p    = (const float*)d_in[7];
    const float* a_r    = (const float*)d_in[8];
    const float* b_r    = (const float*)d_in[9];
    float* out = (float*)d_out;

    gemm_kernel<true><<<dim3(3 * DIM / GBN, MROWS / GBM), 128>>>(x, qkv_w, qkv_b, nullptr);
    attn_kernel<<<dim3(NH, BATCH), 256>>>(D, a_p, b_p, a_r, b_r);
    gemm_kernel<false><<<dim3(DIM / GBN, MROWS / GBM), 128>>>(nullptr, proj_w, proj_b, out);
}

// round 15
// speedup vs baseline: 1.2058x; 1.2058x over previous
#include <cuda_runtime.h>

// ---------------------------------------------------------------------------
// WindowAttention: x(2048,49,192) -> qkv gemm -> 6-head window attention with
// azimuthal + radial sinusoidal biases -> proj gemm.
// Round 14: R13 (packed fma.rn.f32x2 everywhere) with the attention-dot bug
// fixed: loop covered 16/32 head dims (ulonglong2 = 4 floats, needed 8 iters).
// ---------------------------------------------------------------------------

#define WH 7
#define WW 7
#define NWIN 49
#define NH 6
#define HD 32
#define DIM 192
#define BATCH 2048
#define MROWS (BATCH * NWIN)          // 100352
#define QK_SCALE 0.17677669529663687f // 32^-0.5
#define PI_F 3.14159265358979323846f

// Scratch (allocation-free rule: __device__ globals)
__device__ float g_q[(size_t)BATCH * NH * NWIN * HD];
__device__ float g_k[(size_t)BATCH * NH * NWIN * HD];
__device__ float g_v[(size_t)BATCH * NH * NWIN * HD];
__device__ float g_ctx[(size_t)MROWS * DIM];

// ---- packed f32x2 helpers (sm_103a FFMA2) ---------------------------------
__device__ __forceinline__ unsigned long long dup2(float f) {
    unsigned long long r;
    unsigned int u = __float_as_uint(f);
    asm("mov.b64 %0, {%1, %1};" : "=l"(r) : "r"(u));
    return r;
}
__device__ __forceinline__ void fma2(unsigned long long& d,
                                     unsigned long long a,
                                     unsigned long long b) {
    asm("fma.rn.f32x2 %0, %1, %2, %0;" : "+l"(d) : "l"(a), "l"(b));
}
__device__ __forceinline__ float2 unpack2(unsigned long long v) {
    unsigned int lo, hi;
    asm("mov.b64 {%0, %1}, %2;" : "=r"(lo), "=r"(hi) : "l"(v));
    float2 f;
    f.x = __uint_as_float(lo);
    f.y = __uint_as_float(hi);
    return f;
}

// ---------------------------------------------------------------------------
// Tiled SGEMM: out[m][n] = sum_k A[m][k] * W[n][k] (+ bias[n])
// BM=128, BN=64, BK=16, 256 threads. Per thread: 8(m, as 4 packed pairs) x 4(n).
// Inner k-step: 16 FFMA2 + 4 dup-MOV + 3 LDS.128 -> FFMA2-pipe bound.
// QKV=true: A = x, epilogue scatters into g_q (scaled), g_k, g_v.
// QKV=false: A = g_ctx, epilogue writes d_out with bias.
// 100352 = 784*128, 576 = 9*64, 192 = 3*64 = 12*16 -> no bounds checks.
// ---------------------------------------------------------------------------
#define BM 128
#define BN 64
#define BK 16

template <bool QKV>
__global__ __launch_bounds__(256) void gemm_kernel(
    const float* __restrict__ Ain, const float* __restrict__ W,
    const float* __restrict__ bias, float* __restrict__ out)
{
    const float* A = QKV ? Ain : g_ctx;

    __shared__ __align__(16) float As[BK][BM];
    __shared__ __align__(16) float Bs[BK][BN];

    const int tid = threadIdx.x;
    const int ty = tid >> 4;        // 0..15 (row group of 8)
    const int tx = tid & 15;        // 0..15 (col group of 4)
    const int m0 = blockIdx.y * BM;
    const int n0 = blockIdx.x * BN;

    const int lrow = tid >> 2;          // 0..63
    const int lcol = (tid & 3) << 2;    // 0,4,8,12

    const float* Aptr = A + (size_t)(m0 + lrow) * DIM + lcol;
    const float* Wptr = W + (size_t)(n0 + lrow) * DIM + lcol;

    // acc[i2][j]: packed pair of rows (m_base + 2*i2, +1) x column (n_base + j)
    unsigned long long acc[4][4];
#pragma unroll
    for (int i = 0; i < 4; i++)
#pragma unroll
        for (int j = 0; j < 4; j++) acc[i][j] = 0ull;

    for (int kk = 0; kk < DIM; kk += BK) {
        float4 a0 = *(const float4*)(Aptr + kk);
        float4 a1 = *(const float4*)(Aptr + (size_t)64 * DIM + kk);
        float4 b0 = *(const float4*)(Wptr + kk);

        As[lcol + 0][lrow] = a0.x;
        As[lcol + 1][lrow] = a0.y;
        As[lcol + 2][lrow] = a0.z;
        As[lcol + 3][lrow] = a0.w;
        As[lcol + 0][lrow + 64] = a1.x;
        As[lcol + 1][lrow + 64] = a1.y;
        As[lcol + 2][lrow + 64] = a1.z;
        As[lcol + 3][lrow + 64] = a1.w;
        Bs[lcol + 0][lrow] = b0.x;
        Bs[lcol + 1][lrow] = b0.y;
        Bs[lcol + 2][lrow] = b0.z;
        Bs[lcol + 3][lrow] = b0.w;
        __syncthreads();

#pragma unroll
        for (int k = 0; k < BK; k++) {
            // A pairs: adjacent rows packed for free via 16B smem loads
            ulonglong2 aA = *(const ulonglong2*)&As[k][ty * 8];
            ulonglong2 aB = *(const ulonglong2*)&As[k][ty * 8 + 4];
            float4 bv = *(const float4*)&Bs[k][tx * 4];
            unsigned long long ar[4] = {aA.x, aA.y, aB.x, aB.y};
            unsigned long long bd[4] = {dup2(bv.x), dup2(bv.y),
                                        dup2(bv.z), dup2(bv.w)};
#pragma unroll
            for (int i = 0; i < 4; i++)
#pragma unroll
                for (int j = 0; j < 4; j++)
                    fma2(acc[i][j], ar[i], bd[j]);
        }
        __syncthreads();
    }

    const int m_base = m0 + ty * 8;
    const int n_base = n0 + tx * 4;

    if (QKV) {
#pragma unroll
        for (int i2 = 0; i2 < 4; i2++) {
            float2 col[4];
#pragma unroll
            for (int j = 0; j < 4; j++) col[j] = unpack2(acc[i2][j]);
#pragma unroll
            for (int half = 0; half < 2; half++) {
                int m = m_base + 2 * i2 + half;
                int b = m / NWIN;
                int nn = m - b * NWIN;
#pragma unroll
                for (int j = 0; j < 4; j++) {
                    int n = n_base + j;
                    float val = (half ? col[j].y : col[j].x) + bias[n];
                    int which = n / DIM;
                    int rem = n - which * DIM;
                    int h = rem >> 5;
                    int d = rem & 31;
                    size_t idx = (((size_t)b * NH + h) * NWIN + nn) * HD + d;
                    if (which == 0)      g_q[idx] = val * QK_SCALE;
                    else if (which == 1) g_k[idx] = val;
                    else                 g_v[idx] = val;
                }
            }
        }
    } else {
        float4 bb = *(const float4*)&bias[n_base];
#pragma unroll
        for (int i2 = 0; i2 < 4; i2++) {
            float2 c0 = unpack2(acc[i2][0]);
            float2 c1 = unpack2(acc[i2][1]);
            float2 c2 = unpack2(acc[i2][2]);
            float2 c3 = unpack2(acc[i2][3]);
            int m = m_base + 2 * i2;
            float4 o0, o1;
            o0.x = c0.x + bb.x; o0.y = c1.x + bb.y;
            o0.z = c2.x + bb.z; o0.w = c3.x + bb.w;
            o1.x = c0.y + bb.x; o1.y = c1.y + bb.y;
            o1.z = c2.y + bb.z; o1.w = c3.y + bb.w;
            *(float4*)&out[(size_t)m * DIM + n_base] = o0;
            *(float4*)&out[(size_t)(m + 1) * DIM + n_base] = o1;
        }
    }
}

// ---------------------------------------------------------------------------
// Attention: one block per (head h, window b). 256 threads.
// Bias fields collapse to two 13-entry tables (az, rr each in [-6,6]).
// Only 26 sincosf per block. Smem rows padded to 36 floats (16B-aligned).
// Dot products and PV accumulation in packed f32x2.
// ---------------------------------------------------------------------------
__global__ __launch_bounds__(256) void attn_kernel(
    const float* __restrict__ Dptr,
    const float* __restrict__ a_p, const float* __restrict__ b_p,
    const float* __restrict__ a_r, const float* __restrict__ b_r)
{
    const int h = blockIdx.x;
    const int b = blockIdx.y;
    const int tid = threadIdx.x;

    __shared__ __align__(16) float qs[NWIN * 36];
    __shared__ __align__(16) float ks[NWIN * 36];
    __shared__ __align__(16) float vs[NWIN * 36];
    __shared__ float S[NWIN * NWIN];
    __shared__ float biasA[13], biasR[13];

    const size_t base = ((size_t)b * NH + h) * NWIN * HD;

    if (tid < 13) {
        int az = tid - 6;
        int aidx = az < 0 ? az + 13 : az;   // python-style wrap (mod 13)
        float s, c;
        sincosf((float)az * (2.0f * PI_F / 56.0f), &s, &c);
        biasA[tid] = a_p[aidx * NH + h] * c + b_p[aidx * NH + h] * s;
    } else if (tid >= 32 && tid < 45) {
        int v = tid - 32;
        int rr = v - 6;
        int ridx = rr < 0 ? rr + 13 : rr;
        float Db = Dptr[b];
        float s, c;
        sincosf(Db * (float)rr * (2.0f * PI_F / 224.0f), &s, &c);
        biasR[v] = a_r[ridx * NH + h] * c + b_r[ridx * NH + h] * s;
    }
    for (int t = tid; t < NWIN * HD; t += 256) {
        int r = t >> 5, c = t & 31;
        qs[r * 36 + c] = g_q[base + t];
        ks[r * 36 + c] = g_k[base + t];
        vs[r * 36 + c] = g_v[base + t];
    }
    __syncthreads();

    // S = q*k^T (q pre-scaled) + biasA + biasR
    // HD=32 floats = 8 u64 pairs -> 8 fma2 (4 iters x 2 chains)
    for (int t = tid; t < NWIN * NWIN; t += 256) {
        int i = t / NWIN;
        int j = t - i * NWIN;
        const ulonglong2* q2 = (const ulonglong2*)(qs + i * 36);
        const ulonglong2* k2 = (const ulonglong2*)(ks + j * 36);
        unsigned long long d0 = 0ull, d1 = 0ull;
#pragma unroll
        for (int c = 0; c < 8; c++) {       // 8 ulonglong2 = 32 floats (FIXED)
            ulonglong2 qv = q2[c];
            ulonglong2 kv = k2[c];
            fma2(d0, qv.x, kv.x);
            fma2(d1, qv.y, kv.y);
        }
        float2 f0 = unpack2(d0), f1 = unpack2(d1);
        float dot = (f0.x + f0.y) + (f1.x + f1.y);

        int ih = i / WW, iw = i - ih * WW;
        int jh = j / WW, jw = j - jh * WW;
        S[t] = dot + biasA[iw - jw + 6] + biasR[ih - jh + 6];
    }
    __syncthreads();

    // softmax: one warp per row
    const int warp = tid >> 5, lane = tid & 31;
    for (int row = warp; row < NWIN; row += 8) {
        float* Sr = S + row * NWIN;
        float v0 = Sr[lane];
        float v1 = (lane + 32 < NWIN) ? Sr[lane + 32] : -1e30f;
        float mx = fmaxf(v0, v1);
#pragma unroll
        for (int o = 16; o; o >>= 1)
            mx = fmaxf(mx, __shfl_xor_sync(0xffffffffu, mx, o));
        float e0 = expf(v0 - mx);
        float e1 = (lane + 32 < NWIN) ? expf(v1 - mx) : 0.0f;
        float sm = e0 + e1;
#pragma unroll
        for (int o = 16; o; o >>= 1)
            sm += __shfl_xor_sync(0xffffffffu, sm, o);
        float inv = 1.0f / sm;
        Sr[lane] = e0 * inv;
        if (lane + 32 < NWIN) Sr[lane + 32] = e1 * inv;
    }
    __syncthreads();

    // O = P * V -> ctx layout (b, n, h*32 + d). 196 threads, 8 outputs each.
    if (tid < 196) {
        int n = tid >> 2;
        int dq = (tid & 3) << 3;      // 0,8,16,24
        const float* Pr = S + n * NWIN;
        unsigned long long o[4] = {0ull, 0ull, 0ull, 0ull};
#pragma unroll 7
        for (int m2 = 0; m2 < NWIN; m2++) {
            unsigned long long pd = dup2(Pr[m2]);
            const ulonglong2* vr = (const ulonglong2*)&vs[m2 * 36 + dq];
            ulonglong2 v0 = vr[0];
            ulonglong2 v1 = vr[1];
            fma2(o[0], pd, v0.x);
            fma2(o[1], pd, v0.y);
            fma2(o[2], pd, v1.x);
            fma2(o[3], pd, v1.y);
        }
        float2 u0 = unpack2(o[0]), u1 = unpack2(o[1]);
        float2 u2 = unpack2(o[2]), u3 = unpack2(o[3]);
        float4 w0, w1;
        w0.x = u0.x; w0.y = u0.y; w0.z = u1.x; w0.w = u1.y;
        w1.x = u2.x; w1.y = u2.y; w1.z = u3.x; w1.w = u3.y;
        float* ctx = g_ctx + ((size_t)b * NWIN + n) * DIM + h * HD + dq;
        *(float4*)ctx = w0;
        *(float4*)(ctx + 4) = w1;
    }
}

// ---------------------------------------------------------------------------
extern "C" void kernel_launch(void* const* d_in, const int* in_sizes, int n_in,
                              void* d_out, int out_size)
{
    const float* x      = (const float*)d_in[0];
    const float* D      = (const float*)d_in[1];
    const float* qkv_w  = (const float*)d_in[2];
    const float* qkv_b  = (const float*)d_in[3];
    const float* proj_w = (const float*)d_in[4];
    const float* proj_b = (const float*)d_in[5];
    const float* a_p    = (const float*)d_in[6];
    const float* b_p    = (const float*)d_in[7];
    const float* a_r    = (const float*)d_in[8];
    const float* b_r    = (const float*)d_in[9];
    float* out = (float*)d_out;

    gemm_kernel<true><<<dim3(3 * DIM / BN, MROWS / BM), 256>>>(x, qkv_w, qkv_b, nullptr);
    attn_kernel<<<dim3(NH, BATCH), 256>>>(D, a_p, b_p, a_r, b_r);
    gemm_kernel<false><<<dim3(DIM / BN, MROWS / BM), 256>>>(nullptr, proj_w, proj_b, out);
}

// round 17
// speedup vs baseline: 1.6905x; 1.4019x over previous
#include <cuda_runtime.h>
#include <cuda_bf16.h>
#include <cstdint>

// ---------------------------------------------------------------------------
// WindowAttention: x(2048,49,192) -> qkv gemm -> 6-head window attention with
// azimuthal + radial sinusoidal biases -> proj gemm.
// Round 16: tcgen05 rejected by toolchain (PTX targets sm_103, not sm_103a).
// GEMMs use baseline tensor cores instead: ldmatrix + mma.sync.m16n8k16 bf16
// with 3-term hi/lo split (A_hi*B_hi + A_hi*B_lo + A_lo*B_hi, fp32 accum).
// Prologue converts x/weights to bf16 hi/lo once; GEMM blocks keep the whole
// K=192 A-tile resident in smem and loop over N-chunks (x read exactly once).
// Attention epilogue writes ctx directly as bf16 hi/lo for the proj GEMM.
// ---------------------------------------------------------------------------

#define WH 7
#define WW 7
#define NWIN 49
#define NH 6
#define HD 32
#define DIM 192
#define BATCH 2048
#define MROWS (BATCH * NWIN)          // 100352
#define QK_SCALE 0.17677669529663687f // 32^-0.5
#define PI_F 3.14159265358979323846f

// Scratch (allocation-free rule: __device__ globals)
__device__ __nv_bfloat16 g_xh[(size_t)MROWS * DIM];
__device__ __nv_bfloat16 g_xl[(size_t)MROWS * DIM];
__device__ __nv_bfloat16 g_wqh[576 * DIM];
__device__ __nv_bfloat16 g_wql[576 * DIM];
__device__ __nv_bfloat16 g_pwh[DIM * DIM];
__device__ __nv_bfloat16 g_pwl[DIM * DIM];
__device__ float g_q[(size_t)BATCH * NH * NWIN * HD];
__device__ float g_k[(size_t)BATCH * NH * NWIN * HD];
__device__ float g_v[(size_t)BATCH * NH * NWIN * HD];
__device__ __nv_bfloat16 g_ch[(size_t)MROWS * DIM];
__device__ __nv_bfloat16 g_cl[(size_t)MROWS * DIM];

// ---- helpers --------------------------------------------------------------
__device__ __forceinline__ uint32_t pack_bf2(__nv_bfloat16 lo, __nv_bfloat16 hi) {
    return ((uint32_t)__bfloat16_as_ushort(hi) << 16) | __bfloat16_as_ushort(lo);
}
__device__ __forceinline__ void split_bf(float f, __nv_bfloat16& h, __nv_bfloat16& l) {
    h = __float2bfloat16(f);
    l = __float2bfloat16(f - __bfloat162float(h));
}
__device__ __forceinline__ void ldsm4(uint32_t* r, uint32_t addr) {
    asm volatile("ldmatrix.sync.aligned.m8n8.x4.shared.b16 {%0,%1,%2,%3}, [%4];"
                 : "=r"(r[0]), "=r"(r[1]), "=r"(r[2]), "=r"(r[3]) : "r"(addr));
}
__device__ __forceinline__ void mma_bf16(float* c, const uint32_t* a,
                                         uint32_t b0, uint32_t b1) {
    asm volatile(
        "mma.sync.aligned.m16n8k16.row.col.f32.bf16.bf16.f32 "
        "{%0,%1,%2,%3},{%4,%5,%6,%7},{%8,%9},{%0,%1,%2,%3};"
        : "+f"(c[0]), "+f"(c[1]), "+f"(c[2]), "+f"(c[3])
        : "r"(a[0]), "r"(a[1]), "r"(a[2]), "r"(a[3]), "r"(b0), "r"(b1));
}

// ---------------------------------------------------------------------------
// Prologue: fp32 -> bf16 hi/lo split, 2 elements per thread.
// ---------------------------------------------------------------------------
__global__ __launch_bounds__(256) void convert_kernel(
    const float* __restrict__ src, __nv_bfloat16* __restrict__ dh,
    __nv_bfloat16* __restrict__ dl, int n2)
{
    int i = blockIdx.x * 256 + threadIdx.x;
    if (i < n2) {
        float2 f = ((const float2*)src)[i];
        __nv_bfloat16 h0, h1, l0, l1;
        split_bf(f.x, h0, l0);
        split_bf(f.y, h1, l1);
        ((uint32_t*)dh)[i] = pack_bf2(h0, h1);
        ((uint32_t*)dl)[i] = pack_bf2(l0, l1);
    }
}

// ---------------------------------------------------------------------------
// Tensor-core GEMM: C[m][n] = sum_k A[m][k]*W[n][k] (+bias), K=192 whole.
// One CTA per 128-row m-block; A tile (hi+lo) resident in smem; loop over
// NCH chunks of 96 n-cols. 256 threads = 8 warps as 4(m) x 2(n); warp tile
// 32m x 48n = 2 m-tiles x 6 n-tiles of m16n8k16. Smem stride 200 bf16
// (400 B) -> ldmatrix conflict-free. 3 split terms, term-outermost (12
// independent accumulators between reuses).
// QKV=true: epilogue scatters (val+bias)[*scale] into g_q/g_k/g_v.
// QKV=false: epilogue writes out + bias.
// ---------------------------------------------------------------------------
#define SA 200
#define SMEM_GEMM (128*SA*2*2 + 96*SA*2*2 + 576*4)   // 181504

template <int NCH, bool QKV>
__global__ __launch_bounds__(256) void gemm_tc(
    const __nv_bfloat16* __restrict__ Ah, const __nv_bfloat16* __restrict__ Al,
    const __nv_bfloat16* __restrict__ Bh, const __nv_bfloat16* __restrict__ Bl,
    const float* __restrict__ bias, float* __restrict__ out)
{
    extern __shared__ char smem[];
    __nv_bfloat16* sAh = (__nv_bfloat16*)smem;
    __nv_bfloat16* sAl = sAh + 128 * SA;
    __nv_bfloat16* sBh = sAl + 128 * SA;
    __nv_bfloat16* sBl = sBh + 96 * SA;
    float* sbias = (float*)(sBl + 96 * SA);

    const int tid = threadIdx.x, wid = tid >> 5, l = tid & 31;
    const int wm = wid >> 1, wn = wid & 1;
    const int m0 = blockIdx.x * 128;

    // load A tile (128 x 192 bf16 hi/lo), rows 16B-aligned in gmem & smem
    for (int e = tid; e < 128 * 24; e += 256) {
        int row = e / 24, c8 = e - row * 24;
        size_t g = (size_t)(m0 + row) * DIM + c8 * 8;
        *(uint4*)(sAh + row * SA + c8 * 8) = *(const uint4*)(Ah + g);
        *(uint4*)(sAl + row * SA + c8 * 8) = *(const uint4*)(Al + g);
    }
    for (int e = tid; e < NCH * 96; e += 256) sbias[e] = bias[e];

    // per-lane ldmatrix base addresses
    uint32_t aH = (uint32_t)__cvta_generic_to_shared(sAh)
                + 2 * ((wm * 32 + (l & 15)) * SA + ((l >> 4) & 1) * 8);
    uint32_t aL = (uint32_t)__cvta_generic_to_shared(sAl)
                + 2 * ((wm * 32 + (l & 15)) * SA + ((l >> 4) & 1) * 8);
    uint32_t bH = (uint32_t)__cvta_generic_to_shared(sBh)
                + 2 * ((wn * 48 + (l & 7) + ((l >> 4) & 1) * 8) * SA + ((l >> 3) & 1) * 8);
    uint32_t bL = (uint32_t)__cvta_generic_to_shared(sBl)
                + 2 * ((wn * 48 + (l & 7) + ((l >> 4) & 1) * 8) * SA + ((l >> 3) & 1) * 8);

#pragma unroll 1
    for (int ch = 0; ch < NCH; ch++) {
        // load B chunk: 96 rows of this n-chunk (hi/lo)
        for (int e = tid; e < 96 * 24; e += 256) {
            int row = e / 24, c8 = e - row * 24;
            size_t g = (size_t)(ch * 96 + row) * DIM + c8 * 8;
            *(uint4*)(sBh + row * SA + c8 * 8) = *(const uint4*)(Bh + g);
            *(uint4*)(sBl + row * SA + c8 * 8) = *(const uint4*)(Bl + g);
        }
        __syncthreads();

        float c[2][6][4];
#pragma unroll
        for (int i = 0; i < 2; i++)
#pragma unroll
            for (int j = 0; j < 6; j++)
#pragma unroll
                for (int q = 0; q < 4; q++) c[i][j][q] = 0.0f;

#pragma unroll 1
        for (int ks = 0; ks < 12; ks++) {
            const uint32_t ko = 32u * ks;
            uint32_t ah[2][4], alr[2][4], bh2[3][4], bl2[3][4];
            ldsm4(ah[0], aH + ko);
            ldsm4(ah[1], aH + 6400 + ko);
            ldsm4(alr[0], aL + ko);
            ldsm4(alr[1], aL + 6400 + ko);
            ldsm4(bh2[0], bH + ko);
            ldsm4(bh2[1], bH + 6400 + ko);
            ldsm4(bh2[2], bH + 12800 + ko);
            ldsm4(bl2[0], bL + ko);
            ldsm4(bl2[1], bL + 6400 + ko);
            ldsm4(bl2[2], bL + 12800 + ko);
            // term 1: hi*hi (12 independent accumulators)
#pragma unroll
            for (int mt = 0; mt < 2; mt++)
#pragma unroll
                for (int nt = 0; nt < 6; nt++)
                    mma_bf16(c[mt][nt], ah[mt],
                             bh2[nt >> 1][(nt & 1) * 2], bh2[nt >> 1][(nt & 1) * 2 + 1]);
            // term 2: hi*lo
#pragma unroll
            for (int mt = 0; mt < 2; mt++)
#pragma unroll
                for (int nt = 0; nt < 6; nt++)
                    mma_bf16(c[mt][nt], ah[mt],
                             bl2[nt >> 1][(nt & 1) * 2], bl2[nt >> 1][(nt & 1) * 2 + 1]);
            // term 3: lo*hi
#pragma unroll
            for (int mt = 0; mt < 2; mt++)
#pragma unroll
                for (int nt = 0; nt < 6; nt++)
                    mma_bf16(c[mt][nt], alr[mt],
                             bh2[nt >> 1][(nt & 1) * 2], bh2[nt >> 1][(nt & 1) * 2 + 1]);
        }

        // epilogue: C frag (m16n8): c0,c1 = row l>>2, cols 2(l&3),+1; c2,c3 row+8
#pragma unroll
        for (int mt = 0; mt < 2; mt++)
#pragma unroll
            for (int nt = 0; nt < 6; nt++) {
                int n_abs = ch * 96 + wn * 48 + nt * 8 + (l & 3) * 2;
                int m1 = m0 + wm * 32 + mt * 16 + (l >> 2);
                float b0 = sbias[n_abs], b1 = sbias[n_abs + 1];
                float v00 = c[mt][nt][0] + b0, v01 = c[mt][nt][1] + b1;
                float v10 = c[mt][nt][2] + b0, v11 = c[mt][nt][3] + b1;
                if (QKV) {
                    int which = n_abs / 192;
                    int rem = n_abs - which * 192;
                    int h = rem >> 5, d = rem & 31;
                    float sc = (which == 0) ? QK_SCALE : 1.0f;
                    float* dst = which == 0 ? g_q : which == 1 ? g_k : g_v;
                    int b_1 = m1 / NWIN, nn1 = m1 - NWIN * b_1;
                    int m2 = m1 + 8;
                    int b_2 = m2 / NWIN, nn2 = m2 - NWIN * b_2;
                    float2 p0 = {v00 * sc, v01 * sc};
                    float2 p1 = {v10 * sc, v11 * sc};
                    *(float2*)&dst[(((size_t)b_1 * NH + h) * NWIN + nn1) * HD + d] = p0;
                    *(float2*)&dst[(((size_t)b_2 * NH + h) * NWIN + nn2) * HD + d] = p1;
                } else {
                    float2 p0 = {v00, v01};
                    float2 p1 = {v10, v11};
                    *(float2*)&out[(size_t)m1 * DIM + n_abs] = p0;
                    *(float2*)&out[(size_t)(m1 + 8) * DIM + n_abs] = p1;
                }
            }
        __syncthreads();
    }
}

// ---------------------------------------------------------------------------
// Attention: one block per (head h, window b). 256 threads. Same as R15
// (passing, rel_err 1.1e-7) except the epilogue writes ctx as bf16 hi/lo.
// ---------------------------------------------------------------------------
__device__ __forceinline__ unsigned long long dup2(float f) {
    unsigned long long r;
    unsigned int u = __float_as_uint(f);
    asm("mov.b64 %0, {%1, %1};" : "=l"(r) : "r"(u));
    return r;
}
__device__ __forceinline__ void fma2(unsigned long long& d,
                                     unsigned long long a,
                                     unsigned long long b) {
    asm("fma.rn.f32x2 %0, %1, %2, %0;" : "+l"(d) : "l"(a), "l"(b));
}
__device__ __forceinline__ float2 unpack2(unsigned long long v) {
    unsigned int lo, hi;
    asm("mov.b64 {%0, %1}, %2;" : "=r"(lo), "=r"(hi) : "l"(v));
    float2 f;
    f.x = __uint_as_float(lo);
    f.y = __uint_as_float(hi);
    return f;
}

__global__ __launch_bounds__(256) void attn_kernel(
    const float* __restrict__ Dptr,
    const float* __restrict__ a_p, const float* __restrict__ b_p,
    const float* __restrict__ a_r, const float* __restrict__ b_r)
{
    const int h = blockIdx.x;
    const int b = blockIdx.y;
    const int tid = threadIdx.x;

    __shared__ __align__(16) float qs[NWIN * 36];
    __shared__ __align__(16) float ks[NWIN * 36];
    __shared__ __align__(16) float vs[NWIN * 36];
    __shared__ float S[NWIN * NWIN];
    __shared__ float biasA[13], biasR[13];

    const size_t base = ((size_t)b * NH + h) * NWIN * HD;

    if (tid < 13) {
        int az = tid - 6;
        int aidx = az < 0 ? az + 13 : az;
        float s, c;
        sincosf((float)az * (2.0f * PI_F / 56.0f), &s, &c);
        biasA[tid] = a_p[aidx * NH + h] * c + b_p[aidx * NH + h] * s;
    } else if (tid >= 32 && tid < 45) {
        int v = tid - 32;
        int rr = v - 6;
        int ridx = rr < 0 ? rr + 13 : rr;
        float Db = Dptr[b];
        float s, c;
        sincosf(Db * (float)rr * (2.0f * PI_F / 224.0f), &s, &c);
        biasR[v] = a_r[ridx * NH + h] * c + b_r[ridx * NH + h] * s;
    }
    for (int t = tid; t < NWIN * HD; t += 256) {
        int r = t >> 5, c = t & 31;
        qs[r * 36 + c] = g_q[base + t];
        ks[r * 36 + c] = g_k[base + t];
        vs[r * 36 + c] = g_v[base + t];
    }
    __syncthreads();

    for (int t = tid; t < NWIN * NWIN; t += 256) {
        int i = t / NWIN;
        int j = t - i * NWIN;
        const ulonglong2* q2 = (const ulonglong2*)(qs + i * 36);
        const ulonglong2* k2 = (const ulonglong2*)(ks + j * 36);
        unsigned long long d0 = 0ull, d1 = 0ull;
#pragma unroll
        for (int c = 0; c < 8; c++) {
            ulonglong2 qv = q2[c];
            ulonglong2 kv = k2[c];
            fma2(d0, qv.x, kv.x);
            fma2(d1, qv.y, kv.y);
        }
        float2 f0 = unpack2(d0), f1 = unpack2(d1);
        float dot = (f0.x + f0.y) + (f1.x + f1.y);

        int ih = i / WW, iw = i - ih * WW;
        int jh = j / WW, jw = j - jh * WW;
        S[t] = dot + biasA[iw - jw + 6] + biasR[ih - jh + 6];
    }
    __syncthreads();

    const int warp = tid >> 5, lane = tid & 31;
    for (int row = warp; row < NWIN; row += 8) {
        float* Sr = S + row * NWIN;
        float v0 = Sr[lane];
        float v1 = (lane + 32 < NWIN) ? Sr[lane + 32] : -1e30f;
        float mx = fmaxf(v0, v1);
#pragma unroll
        for (int o = 16; o; o >>= 1)
            mx = fmaxf(mx, __shfl_xor_sync(0xffffffffu, mx, o));
        float e0 = expf(v0 - mx);
        float e1 = (lane + 32 < NWIN) ? expf(v1 - mx) : 0.0f;
        float sm = e0 + e1;
#pragma unroll
        for (int o = 16; o; o >>= 1)
            sm += __shfl_xor_sync(0xffffffffu, sm, o);
        float inv = 1.0f / sm;
        Sr[lane] = e0 * inv;
        if (lane + 32 < NWIN) Sr[lane + 32] = e1 * inv;
    }
    __syncthreads();

    // O = P * V -> ctx written as bf16 hi/lo for the proj tensor-core GEMM.
    if (tid < 196) {
        int n = tid >> 2;
        int dq = (tid & 3) << 3;
        const float* Pr = S + n * NWIN;
        unsigned long long o[4] = {0ull, 0ull, 0ull, 0ull};
#pragma unroll 7
        for (int m2 = 0; m2 < NWIN; m2++) {
            unsigned long long pd = dup2(Pr[m2]);
            const ulonglong2* vr = (const ulonglong2*)&vs[m2 * 36 + dq];
            ulonglong2 v0 = vr[0];
            ulonglong2 v1 = vr[1];
            fma2(o[0], pd, v0.x);
            fma2(o[1], pd, v0.y);
            fma2(o[2], pd, v1.x);
            fma2(o[3], pd, v1.y);
        }
        float v[8];
        float2 u;
        u = unpack2(o[0]); v[0] = u.x; v[1] = u.y;
        u = unpack2(o[1]); v[2] = u.x; v[3] = u.y;
        u = unpack2(o[2]); v[4] = u.x; v[5] = u.y;
        u = unpack2(o[3]); v[6] = u.x; v[7] = u.y;
        uint4 ph, pl;
        uint32_t* php = (uint32_t*)&ph;
        uint32_t* plp = (uint32_t*)&pl;
#pragma unroll
        for (int i = 0; i < 4; i++) {
            __nv_bfloat16 h0, h1, l0, l1;
            split_bf(v[2 * i], h0, l0);
            split_bf(v[2 * i + 1], h1, l1);
            php[i] = pack_bf2(h0, h1);
            plp[i] = pack_bf2(l0, l1);
        }
        size_t off = ((size_t)b * NWIN + n) * DIM + h * HD + dq;
        *(uint4*)&g_ch[off] = ph;
        *(uint4*)&g_cl[off] = pl;
    }
}

// ---------------------------------------------------------------------------
extern "C" void kernel_launch(void* const* d_in, const int* in_sizes, int n_in,
                              void* d_out, int out_size)
{
    const float* x      = (const float*)d_in[0];
    const float* D      = (const float*)d_in[1];
    const float* qkv_w  = (const float*)d_in[2];
    const float* qkv_b  = (const float*)d_in[3];
    const float* proj_w = (const float*)d_in[4];
    const float* proj_b = (const float*)d_in[5];
    const float* a_p    = (const float*)d_in[6];
    const float* b_p    = (const float*)d_in[7];
    const float* a_r    = (const float*)d_in[8];
    const float* b_r    = (const float*)d_in[9];
    float* out = (float*)d_out;

    cudaFuncSetAttribute(gemm_tc<6, true>,
                         cudaFuncAttributeMaxDynamicSharedMemorySize, SMEM_GEMM);
    cudaFuncSetAttribute(gemm_tc<2, false>,
                         cudaFuncAttributeMaxDynamicSharedMemorySize, SMEM_GEMM);

    __nv_bfloat16 *xh, *xl, *wqh, *wql, *pwh, *pwl;
    cudaGetSymbolAddress((void**)&xh, g_xh);
    cudaGetSymbolAddress((void**)&xl, g_xl);
    cudaGetSymbolAddress((void**)&wqh, g_wqh);
    cudaGetSymbolAddress((void**)&wql, g_wql);
    cudaGetSymbolAddress((void**)&pwh, g_pwh);
    cudaGetSymbolAddress((void**)&pwl, g_pwl);
    __nv_bfloat16 *ch, *cl;
    cudaGetSymbolAddress((void**)&ch, g_ch);
    cudaGetSymbolAddress((void**)&cl, g_cl);

    // prologue: hi/lo bf16 conversion
    convert_kernel<<<(MROWS * DIM / 2 + 255) / 256, 256>>>(x, xh, xl, MROWS * DIM / 2);
    convert_kernel<<<(576 * DIM / 2 + 255) / 256, 256>>>(qkv_w, wqh, wql, 576 * DIM / 2);
    convert_kernel<<<(DIM * DIM / 2 + 255) / 256, 256>>>(proj_w, pwh, pwl, DIM * DIM / 2);

    gemm_tc<6, true><<<MROWS / 128, 256, SMEM_GEMM>>>(xh, xl, wqh, wql, qkv_b, nullptr);
    attn_kernel<<<dim3(NH, BATCH), 256>>>(D, a_p, b_p, a_r, b_r);
    gemm_tc<2, false><<<MROWS / 128, 256, SMEM_GEMM>>>(ch, cl, pwh, pwl, proj_b, out);
}